// round 7
// baseline (speedup 1.0000x reference)
#include <cuda_runtime.h>
#include <math.h>

#define BLOCK 256
#define MAX_BLOCKS 8192

__device__ float g_partials[MAX_BLOCKS];
__device__ unsigned int g_count = 0;

// Antiderivative of clamp(x, -hw, hw):  G(x) = 0.5*clamp(x)^2 + hw*max(|x|-hw, 0)
__device__ __forceinline__ float boxG(float x, float hw) {
    float c = fminf(fmaxf(x, -hw), hw);
    float e = fmaxf(fabsf(x) - hw, 0.0f);
    return fmaf(hw, e, 0.5f * c * c);
}

// Contribution of one box2 edge (start P, direction D, t in [0,1]) to the
// clamp-curve area integral; kxy = Dy * rdx (precomputed, shared by the
// opposite edge since signs cancel).
__device__ __forceinline__ float edge_int(float Px, float Py,
                                          float Dx, float Dy,
                                          float rdy, float kxy,
                                          float hw, float hh) {
    float tA = (hh - Py) * rdy;
    float tB = (-hh - Py) * rdy;
    float A = __saturatef(fminf(tA, tB));
    float B = __saturatef(fmaxf(tA, tB));
    float xA = fmaf(A, Dx, Px);
    float xB = fmaf(B, Dx, Px);
    return kxy * (boxG(xB, hw) - boxG(xA, hw));
}

// Reciprocal with degeneracy clamp: rcp(±0)=±inf -> clamped to ±1e8,
// sign preserved. 1 MUFU + 2 min/max.
__device__ __forceinline__ float safe_rcp(float d) {
    float r = __frcp_rn(d);
    return fminf(fmaxf(r, -1e8f), 1e8f);
}

__global__ void __launch_bounds__(BLOCK)
rot_iou_loss_kernel(const float* __restrict__ pred,
                    const float* __restrict__ tgt,
                    float* __restrict__ out,
                    int n, int nblocks, float inv_n) {
    __shared__ float sp[BLOCK * 5];
    __shared__ float st[BLOCK * 5];

    int tid = threadIdx.x;
    long long base = (long long)blockIdx.x * (BLOCK * 5);
    long long total = 5ll * n;
    // coalesced staging: 5 full-warp 128B line loads per array
#pragma unroll
    for (int k = 0; k < 5; k++) {
        long long g = base + k * BLOCK + tid;
        int l = k * BLOCK + tid;
        if (g < total) {
            sp[l] = pred[g];
            st[l] = tgt[g];
        }
    }
    __syncthreads();

    int i = blockIdx.x * BLOCK + tid;
    float loss = 0.0f;
    if (i < n) {
        const float* p = sp + 5 * tid;  // stride-5 LDS: conflict-free (gcd(5,32)=1)
        const float* t = st + 5 * tid;
        float x1 = p[0], y1 = p[1], w1 = p[2], h1 = p[3], a1 = p[4];
        float x2 = t[0], y2 = t[1], w2 = t[2], h2 = t[3], a2 = t[4];

        float area1 = w1 * h1;
        float area2 = w2 * h2;

        // Box1's local frame: box1 -> axis-aligned [-hw,hw]x[-hh,hh].
        float s1, c1;
        __sincosf(a1, &s1, &c1);
        float rx = x2 - x1, ry = y2 - y1;
        float cx = rx * c1 + ry * s1;
        float cy = -rx * s1 + ry * c1;
        float sr, cr;
        __sincosf(a2 - a1, &sr, &cr);
        float hw2 = 0.5f * w2, hh2 = 0.5f * h2;
        float e1x = hw2 * cr, e1y = hw2 * sr;
        float e2x = -hh2 * sr, e2y = hh2 * cr;

        // box2 corners (CCW) in box1 frame
        float q0x = cx - e1x - e2x, q0y = cy - e1y - e2y;
        float q1x = cx + e1x - e2x, q1y = cy + e1y - e2y;
        float q2x = cx + e1x + e2x, q2y = cy + e1y + e2y;
        float q3x = cx - e1x + e2x, q3y = cy - e1y + e2y;

        // Edge dirs: edge0 = 2*e1, edge1 = 2*e2; edges 2,3 are negations.
        float D1x = 2.0f * e1x, D1y = 2.0f * e1y;
        float D2x = 2.0f * e2x, D2y = 2.0f * e2y;
        float r1x = safe_rcp(D1x), r1y = safe_rcp(D1y);
        float r2x = safe_rcp(D2x), r2y = safe_rcp(D2y);
        float k1 = D1y * r1x;  // shared by edges 0 & 2 (signs cancel)
        float k2 = D2y * r2x;  // shared by edges 1 & 3

        float hw = 0.5f * w1, hh = 0.5f * h1;

        // Four independent analytic edge integrals (wide DAG -> ILP).
        float i0 = edge_int(q0x, q0y,  D1x,  D1y,  r1y, k1, hw, hh);
        float i1 = edge_int(q1x, q1y,  D2x,  D2y,  r2y, k2, hw, hh);
        float i2 = edge_int(q2x, q2y, -D1x, -D1y, -r1y, k1, hw, hh);
        float i3 = edge_int(q3x, q3y, -D2x, -D2y, -r2y, k2, hw, hh);

        float inter = fabsf((i0 + i2) + (i1 + i3));

        float iou = __fdividef(inter, area1 + area2 - inter);
        iou = fmaxf(iou, 1e-6f);
        loss = 1.0f - iou * iou * iou;
    }

    // in-block reduction (fixed order -> deterministic)
    __shared__ float sdata[BLOCK / 32];
    float v = loss;
#pragma unroll
    for (int off = 16; off > 0; off >>= 1)
        v += __shfl_down_sync(0xFFFFFFFFu, v, off);
    if ((tid & 31) == 0) sdata[tid >> 5] = v;
    __syncthreads();
    if (tid < 32) {
        float w = (tid < BLOCK / 32) ? sdata[tid] : 0.0f;
#pragma unroll
        for (int off = 4; off > 0; off >>= 1)
            w += __shfl_down_sync(0xFFFFFFFFu, w, off);
        if (tid == 0) g_partials[blockIdx.x] = w;
    }

    // last-block final reduction (deterministic index-order sum)
    __shared__ bool is_last;
    __threadfence();
    if (tid == 0) {
        unsigned int c = atomicAdd(&g_count, 1u);
        is_last = (c == (unsigned int)nblocks - 1u);
    }
    __syncthreads();
    if (is_last) {
        __shared__ double dd[BLOCK];
        double s = 0.0;
        for (int k = tid; k < nblocks; k += BLOCK) s += (double)g_partials[k];
        dd[tid] = s;
        __syncthreads();
#pragma unroll
        for (int stp = BLOCK / 2; stp > 0; stp >>= 1) {
            if (tid < stp) dd[tid] += dd[tid + stp];
            __syncthreads();
        }
        if (tid == 0) {
            out[0] = (float)(dd[0] * (double)inv_n);
            g_count = 0;  // reset for next graph replay
        }
    }
}

extern "C" void kernel_launch(void* const* d_in, const int* in_sizes, int n_in,
                              void* d_out, int out_size) {
    const float* pred = (const float*)d_in[0];
    const float* tgt  = (const float*)d_in[1];
    int n = in_sizes[0] / 5;
    int nblocks = (n + BLOCK - 1) / BLOCK;
    rot_iou_loss_kernel<<<nblocks, BLOCK>>>(pred, tgt, (float*)d_out,
                                            n, nblocks, 1.0f / (float)n);
}

// round 8
// speedup vs baseline: 1.1836x; 1.1836x over previous
#include <cuda_runtime.h>
#include <math.h>

#define BLOCK 256
#define MAX_BLOCKS 8192

__device__ float g_partials[MAX_BLOCKS];
__device__ unsigned int g_count = 0;

// Antiderivative of clamp(x, -hw, hw):  G(x) = 0.5*clamp(x)^2 + hw*max(|x|-hw, 0)
__device__ __forceinline__ float boxG(float x, float hw) {
    float c = fminf(fmaxf(x, -hw), hw);
    float e = fmaxf(fabsf(x) - hw, 0.0f);
    return fmaf(hw, e, 0.5f * c * c);
}

// One box2 edge's contribution to the clamp-curve area integral.
__device__ __forceinline__ float edge_int(float Px, float Py,
                                          float Dx, float Dy,
                                          float rdy, float kxy,
                                          float hw, float hh) {
    float tA = (hh - Py) * rdy;
    float tB = (-hh - Py) * rdy;
    float A = __saturatef(fminf(tA, tB));
    float B = __saturatef(fmaxf(tA, tB));
    float xA = fmaf(A, Dx, Px);
    float xB = fmaf(B, Dx, Px);
    return kxy * (boxG(xB, hw) - boxG(xA, hw));
}

// rcp with degeneracy clamp: ±inf -> ±1e8, sign preserved.
__device__ __forceinline__ float safe_rcp(float d) {
    float r = __frcp_rn(d);
    return fminf(fmaxf(r, -1e8f), 1e8f);
}

// Fully branchless per-element loss (single basic block when inlined).
__device__ __forceinline__ float pair_loss(const float* __restrict__ pred,
                                           const float* __restrict__ tgt,
                                           int i) {
    const float* p = pred + 5ll * i;
    const float* t = tgt + 5ll * i;
    float x1 = p[0], y1 = p[1], w1 = p[2], h1 = p[3], a1 = p[4];
    float x2 = t[0], y2 = t[1], w2 = t[2], h2 = t[3], a2 = t[4];

    float area1 = w1 * h1;
    float area2 = w2 * h2;

    float s1, c1;
    __sincosf(a1, &s1, &c1);
    float rx = x2 - x1, ry = y2 - y1;
    float cx = rx * c1 + ry * s1;
    float cy = -rx * s1 + ry * c1;
    float sr, cr;
    __sincosf(a2 - a1, &sr, &cr);
    float hw2 = 0.5f * w2, hh2 = 0.5f * h2;
    float e1x = hw2 * cr, e1y = hw2 * sr;
    float e2x = -hh2 * sr, e2y = hh2 * cr;

    float q0x = cx - e1x - e2x, q0y = cy - e1y - e2y;
    float q1x = cx + e1x - e2x, q1y = cy + e1y - e2y;
    float q2x = cx + e1x + e2x, q2y = cy + e1y + e2y;
    float q3x = cx - e1x + e2x, q3y = cy - e1y + e2y;

    float D1x = 2.0f * e1x, D1y = 2.0f * e1y;
    float D2x = 2.0f * e2x, D2y = 2.0f * e2y;
    float r1x = safe_rcp(D1x), r1y = safe_rcp(D1y);
    float r2x = safe_rcp(D2x), r2y = safe_rcp(D2y);
    float k1 = D1y * r1x;  // shared by edges 0 & 2 (signs cancel)
    float k2 = D2y * r2x;  // shared by edges 1 & 3

    float hw = 0.5f * w1, hh = 0.5f * h1;

    float i0 = edge_int(q0x, q0y,  D1x,  D1y,  r1y, k1, hw, hh);
    float i1 = edge_int(q1x, q1y,  D2x,  D2y,  r2y, k2, hw, hh);
    float i2 = edge_int(q2x, q2y, -D1x, -D1y, -r1y, k1, hw, hh);
    float i3 = edge_int(q3x, q3y, -D2x, -D2y, -r2y, k2, hw, hh);

    float inter = fabsf((i0 + i2) + (i1 + i3));

    float iou = __fdividef(inter, area1 + area2 - inter);
    iou = fmaxf(iou, 1e-6f);
    return 1.0f - iou * iou * iou;
}

__global__ void __launch_bounds__(BLOCK)
rot_iou_loss_kernel(const float* __restrict__ pred,
                    const float* __restrict__ tgt,
                    float* __restrict__ out,
                    int n, int nblocks, float inv_n) {
    int tid = threadIdx.x;
    int j = blockIdx.x * BLOCK + tid;
    int half = (n + 1) >> 1;

    // Two elements per thread, computed UNCONDITIONALLY (clamped indices,
    // masked results) -> single basic block -> ptxas interleaves the two
    // independent dependency chains.
    int ja = min(j, half - 1);
    int jb = min(j + half, n - 1);
    float ma = (j < half) ? 1.0f : 0.0f;
    float mb = (j < half && j + half < n) ? 1.0f : 0.0f;

    float la = pair_loss(pred, tgt, ja);
    float lb = pair_loss(pred, tgt, jb);
    float loss = fmaf(ma, la, mb * lb);

    // in-block reduction (fixed order -> deterministic)
    __shared__ float sdata[BLOCK / 32];
    float v = loss;
#pragma unroll
    for (int off = 16; off > 0; off >>= 1)
        v += __shfl_down_sync(0xFFFFFFFFu, v, off);
    if ((tid & 31) == 0) sdata[tid >> 5] = v;
    __syncthreads();
    if (tid < 32) {
        float w = (tid < BLOCK / 32) ? sdata[tid] : 0.0f;
#pragma unroll
        for (int off = 4; off > 0; off >>= 1)
            w += __shfl_down_sync(0xFFFFFFFFu, w, off);
        if (tid == 0) g_partials[blockIdx.x] = w;
    }

    // last-block final reduction (deterministic index-order sum)
    __shared__ bool is_last;
    __threadfence();
    if (tid == 0) {
        unsigned int c = atomicAdd(&g_count, 1u);
        is_last = (c == (unsigned int)nblocks - 1u);
    }
    __syncthreads();
    if (is_last) {
        __shared__ double dd[BLOCK];
        double s = 0.0;
        for (int k = tid; k < nblocks; k += BLOCK) s += (double)g_partials[k];
        dd[tid] = s;
        __syncthreads();
#pragma unroll
        for (int st = BLOCK / 2; st > 0; st >>= 1) {
            if (tid < st) dd[tid] += dd[tid + st];
            __syncthreads();
        }
        if (tid == 0) {
            out[0] = (float)(dd[0] * (double)inv_n);
            g_count = 0;  // reset for next graph replay
        }
    }
}

extern "C" void kernel_launch(void* const* d_in, const int* in_sizes, int n_in,
                              void* d_out, int out_size) {
    const float* pred = (const float*)d_in[0];
    const float* tgt  = (const float*)d_in[1];
    int n = in_sizes[0] / 5;
    int half = (n + 1) >> 1;
    int nblocks = (half + BLOCK - 1) / BLOCK;
    rot_iou_loss_kernel<<<nblocks, BLOCK>>>(pred, tgt, (float*)d_out,
                                            n, nblocks, 1.0f / (float)n);
}